// round 15
// baseline (speedup 1.0000x reference)
#include <cuda_runtime.h>
#include <cstdint>
#include <math_constants.h>

#define N_NODES 32768
#define N_PER   512
#define BGRAPH  64
#define E_EDGES 524288
#define C_IN    32
#define HDIM    128
#define KTLS    8
#define A_DIM   8
#define NSLOTS  512
#define ECAP    1024

// ---------------- scratch (device globals; no allocs allowed) ----------------
__device__ float g_as[N_NODES];
__device__ float g_ad[N_NODES];
__device__ int   g_cur[NSLOTS];          // zero-init at load; k_agg re-zeros
__device__ int   g_srcs[NSLOTS * ECAP];
__device__ int   g_done;                 // gemm2 completion counter; k_pre zeroes
__device__ __align__(16) float g_feats[BGRAPH * 1024];
__device__ __align__(16) float g_h1[BGRAPH * 2048];   // RED-accumulated, pre-bias
__device__ __align__(16) float g_h2[BGRAPH * 512];

union F4U { float4 v; unsigned long long u[2]; float f[4]; };

__device__ __forceinline__ void red_add_v4(float* addr, float a, float b, float c, float d) {
    asm volatile("red.global.add.v4.f32 [%0], {%1,%2,%3,%4};"
                 :: "l"(addr), "f"(a), "f"(b), "f"(c), "f"(d) : "memory");
}

// ---------------- fused prefetch + att + edge-filter + zero kernel ------------
// blocks [0,82): L2-prefetch weights (incl. W3); [82,210): att scalars;
// [210,2260): edge filter; [2260,2420): zero h1/h2 (+ g_done)
__global__ void k_pre(const float* __restrict__ x, const float* __restrict__ W,
                      const float* __restrict__ att_src, const float* __restrict__ att_dst,
                      const int* __restrict__ ei, const int* __restrict__ tls,
                      const float* __restrict__ vW1, const float* __restrict__ aW1,
                      const float* __restrict__ vW2, const float* __restrict__ aW2,
                      const float* __restrict__ vW3, const float* __restrict__ aW3) {
    __shared__ float ws[C_IN], wd[C_IN];
    __shared__ int tl[KTLS];
    __shared__ unsigned bm[16];          // 512-bit membership bitmap over local idx
    int t = threadIdx.x;
    if (blockIdx.x < 82) {
        // prefetch weights into L2: 82944 lines of 128B, 4 per thread
        int base = (blockIdx.x * 256 + t) * 4;
#pragma unroll
        for (int q = 0; q < 4; q++) {
            int L = base + q;
            if (L < 82944) {
                const float* p;
                if (L < 32768)      p = vW1 + (long)L * 32;
                else if (L < 65536) p = aW1 + (long)(L - 32768) * 32;
                else if (L < 73728) p = vW2 + (long)(L - 65536) * 32;
                else if (L < 81920) p = aW2 + (long)(L - 73728) * 32;
                else if (L < 82432) p = vW3 + (long)(L - 81920) * 32;
                else                p = aW3 + (long)(L - 82432) * 32;
                asm volatile("prefetch.global.L2 [%0];" :: "l"(p));
            }
        }
    } else if (blockIdx.x < 210) {
        if (t < 64) {
            int c = t & 31;
            const float* av = (t < 32) ? att_src : att_dst;
            float s = 0.f;
#pragma unroll 8
            for (int d = 0; d < HDIM; d++) s = fmaf(W[c * HDIM + d], av[d], s);
            if (t < 32) ws[c] = s; else wd[c] = s;
        }
        __syncthreads();
        int n = (blockIdx.x - 82) * 256 + t;
        const float4* xr = (const float4*)(x + n * C_IN);
        float s1 = 0.f, s2 = 0.f;
#pragma unroll
        for (int q = 0; q < 8; q++) {
            float4 v = xr[q];
            s1 = fmaf(v.x, ws[q*4+0], s1); s2 = fmaf(v.x, wd[q*4+0], s2);
            s1 = fmaf(v.y, ws[q*4+1], s1); s2 = fmaf(v.y, wd[q*4+1], s2);
            s1 = fmaf(v.z, ws[q*4+2], s1); s2 = fmaf(v.z, wd[q*4+2], s2);
            s1 = fmaf(v.w, ws[q*4+3], s1); s2 = fmaf(v.w, wd[q*4+3], s2);
        }
        g_as[n] = s1;
        g_ad[n] = s2;
    } else if (blockIdx.x < 2260) {
        if (t < 16) bm[t] = 0u;
        if (t < KTLS) tl[t] = tls[t];
        __syncthreads();
        if (t < KTLS) atomicOr(&bm[tl[t] >> 5], 1u << (tl[t] & 31));
        __syncthreads();
        long i = (long)(blockIdx.x - 210) * 256 + t;     // < 524800 exactly
        if (i < E_EDGES) {
            int d = ei[E_EDGES + i];
            int loc = d & (N_PER - 1);
            if ((bm[loc >> 5] >> (loc & 31)) & 1u) {      // ~1.7% hit rate
                int b = d >> 9;
                int s = ei[i];
#pragma unroll
                for (int k = 0; k < KTLS; k++) {
                    if (tl[k] == loc) {
                        int slot = b * KTLS + k;
                        int p = atomicAdd(&g_cur[slot], 1);
                        if (p < ECAP) g_srcs[slot * ECAP + p] = s;
                    }
                }
            }
        } else {                                          // self loops
            int slot = (int)(i - E_EDGES);
            int b = slot >> 3, k = slot & 7;
            int n = b * N_PER + tl[k];
            int p = atomicAdd(&g_cur[slot], 1);
            if (p < ECAP) g_srcs[slot * ECAP + p] = n;
        }
    } else {
        if (blockIdx.x == 2260 && t == 0) g_done = 0;
        int i = (blockIdx.x - 2260) * 256 + t;            // < 40960 float4s
        float4 z = make_float4(0.f, 0.f, 0.f, 0.f);
        if (i < 32768)        ((float4*)g_h1)[i] = z;
        else if (i < 40960)   ((float4*)g_h2)[i - 32768] = z;
    }
}

// ---------------- per-target softmax + aggregation -> feats (256 thr) --------
__global__ void __launch_bounds__(256) k_agg(
        const float* __restrict__ x, const float* __restrict__ W,
        const int* __restrict__ tls, const float* __restrict__ b_gat) {
    __shared__ float Ws[C_IN * HDIM];      // 16 KB
    __shared__ float e_s[ECAP];            // 4 KB
    __shared__ int   s_s[ECAP];            // 4 KB
    __shared__ float racc[8][HDIM];        // 4 KB
    __shared__ float rden[8];
    __shared__ float red8[8];
    __shared__ float m_sh;

    int slot = blockIdx.x;
    int b = slot >> 3, k = slot & 7;
    int t = threadIdx.x;
    int w = t >> 5, l = t & 31;
    int n = b * N_PER + tls[k];
    float ad_n = g_ad[n];
    int deg = g_cur[slot];
    if (deg > ECAP) deg = ECAP;

    {
        const float4* Wg = (const float4*)W;
        float4* Wl = (float4*)Ws;
        for (int u = t; u < C_IN * HDIM / 4; u += 256) Wl[u] = Wg[u];
    }

    float lmax = -CUDART_INF_F;
    for (int j = t; j < deg; j += 256) {
        int s = g_srcs[slot * ECAP + j];
        float e = g_as[s] + ad_n;
        e = e > 0.f ? e : 0.2f * e;
        e_s[j] = e;
        s_s[j] = s;
        lmax = fmaxf(lmax, e);
    }
#pragma unroll
    for (int off = 16; off; off >>= 1)
        lmax = fmaxf(lmax, __shfl_xor_sync(0xFFFFFFFFu, lmax, off));
    if (l == 0) red8[w] = lmax;
    __syncthreads();
    if (t == 0) {
        float m0 = fmaxf(fmaxf(red8[0], red8[1]), fmaxf(red8[2], red8[3]));
        float m1 = fmaxf(fmaxf(red8[4], red8[5]), fmaxf(red8[6], red8[7]));
        m_sh = fmaxf(m0, m1);
    }
    __syncthreads();
    float m = m_sh;

    float4 acc = make_float4(0.f, 0.f, 0.f, 0.f);
    float den = 0.f;
    const float4* Ws4 = (const float4*)Ws;
    for (int j = w; j < deg; j += 8) {
        int s = s_s[j];
        float ex = __expf(e_s[j] - m);
        den += ex;
        float xv = x[s * C_IN + l];
        float4 h = make_float4(0.f, 0.f, 0.f, 0.f);
#pragma unroll
        for (int c = 0; c < C_IN; c++) {
            float xc = __shfl_sync(0xFFFFFFFFu, xv, c);
            float4 wv = Ws4[c * 32 + l];
            h.x = fmaf(xc, wv.x, h.x);
            h.y = fmaf(xc, wv.y, h.y);
            h.z = fmaf(xc, wv.z, h.z);
            h.w = fmaf(xc, wv.w, h.w);
        }
        acc.x = fmaf(ex, h.x, acc.x);
        acc.y = fmaf(ex, h.y, acc.y);
        acc.z = fmaf(ex, h.z, acc.z);
        acc.w = fmaf(ex, h.w, acc.w);
    }
    *((float4*)&racc[w][4 * l]) = acc;
    if (l == 0) rden[w] = den;
    __syncthreads();

    if (t < HDIM) {
        float tot = ((racc[0][t] + racc[1][t]) + (racc[2][t] + racc[3][t]))
                  + ((racc[4][t] + racc[5][t]) + (racc[6][t] + racc[7][t]));
        float dtot = ((rden[0] + rden[1]) + (rden[2] + rden[3]))
                   + ((rden[4] + rden[5]) + (rden[6] + rden[7]));
        float v = tot / (dtot + 1e-16f) + b_gat[t];
        v = v > 0.f ? v : expm1f(v);
        g_feats[b * (KTLS * HDIM) + k * HDIM + t] = v;
    }
    if (t == 0) g_cur[slot] = 0;       // reset cursor for next graph replay
}

// ---------------- split-K SGEMM, RED accumulation into pre-zeroed output ------
// Block tile: 64 rows x 64 cols x KC. 128 threads, thread tile 8x4 (f32x2 row pairs).
#define AS_STRIDE 68
#define WS_STRIDE 68

template <int KC>
__global__ void __launch_bounds__(128) k_gemm(
        const float* __restrict__ Ain, int fuse, int ldin, int zstride,
        const float* __restrict__ bv_in, const float* __restrict__ ba_in,
        const float* __restrict__ Wv, const float* __restrict__ Wa,
        float* __restrict__ O, int Nhead) {
    __shared__ float As[KC * AS_STRIDE];
    __shared__ float Ws[KC * WS_STRIDE];

    int z  = blockIdx.z;
    const float* Wg = z ? Wa : Wv;
    int k0 = blockIdx.y * KC;
    int j0 = blockIdx.x * 64;
    int tid = threadIdx.x;

    {
        constexpr int KQ = KC / 4;
        int colbase = z * zstride + k0;
        const float* bin = z ? ba_in : bv_in;
        for (int e = tid; e < 64 * KQ; e += 128) {
            int r = e / KQ, kq = e % KQ;
            float4 v = *(const float4*)(Ain + (long)r * ldin + colbase + kq * 4);
            if (fuse) {
                float4 bb = *(const float4*)(bin + k0 + kq * 4);
                v.x = fmaxf(v.x + bb.x, 0.f);
                v.y = fmaxf(v.y + bb.y, 0.f);
                v.z = fmaxf(v.z + bb.z, 0.f);
                v.w = fmaxf(v.w + bb.w, 0.f);
            }
            As[(kq * 4 + 0) * AS_STRIDE + r] = v.x;
            As[(kq * 4 + 1) * AS_STRIDE + r] = v.y;
            As[(kq * 4 + 2) * AS_STRIDE + r] = v.z;
            As[(kq * 4 + 3) * AS_STRIDE + r] = v.w;
        }
    }
    for (int e = tid; e < KC * 16; e += 128) {
        int kk = e >> 4, jq = e & 15;
        float4 v = *(const float4*)(Wg + (long)(k0 + kk) * Nhead + j0 + jq * 4);
        *(float4*)&Ws[kk * WS_STRIDE + jq * 4] = v;
    }
    __syncthreads();

    int r0 = (tid >> 4) * 8;
    int jb = (tid & 15) * 4;

    unsigned long long acc[4][4];
#pragma unroll
    for (int i = 0; i < 4; i++)
#pragma unroll
        for (int j = 0; j < 4; j++) acc[i][j] = 0ull;

#pragma unroll 8
    for (int kk = 0; kk < KC; kk++) {
        F4U a0, a1, w;
        a0.v = *(float4*)&As[kk * AS_STRIDE + r0];
        a1.v = *(float4*)&As[kk * AS_STRIDE + r0 + 4];
        w.v  = *(float4*)&Ws[kk * WS_STRIDE + jb];
        unsigned long long ap[4] = {a0.u[0], a0.u[1], a1.u[0], a1.u[1]};
#pragma unroll
        for (int j = 0; j < 4; j++) {
            unsigned long long wd;
            asm("mov.b64 %0, {%1, %1};" : "=l"(wd) : "f"(w.f[j]));
            asm("fma.rn.f32x2 %0, %1, %2, %0;" : "+l"(acc[0][j]) : "l"(ap[0]), "l"(wd));
            asm("fma.rn.f32x2 %0, %1, %2, %0;" : "+l"(acc[1][j]) : "l"(ap[1]), "l"(wd));
            asm("fma.rn.f32x2 %0, %1, %2, %0;" : "+l"(acc[2][j]) : "l"(ap[2]), "l"(wd));
            asm("fma.rn.f32x2 %0, %1, %2, %0;" : "+l"(acc[3][j]) : "l"(ap[3]), "l"(wd));
        }
    }

    int ntot = 2 * Nhead;
    float* obase = O + z * Nhead + j0 + jb;
#pragma unroll
    for (int rp = 0; rp < 4; rp++) {
        float lo[4], hi[4];
#pragma unroll
        for (int j = 0; j < 4; j++)
            asm("mov.b64 {%0, %1}, %2;" : "=f"(lo[j]), "=f"(hi[j]) : "l"(acc[rp][j]));
        red_add_v4(obase + (long)(r0 + 2 * rp)     * ntot, lo[0], lo[1], lo[2], lo[3]);
        red_add_v4(obase + (long)(r0 + 2 * rp + 1) * ntot, hi[0], hi[1], hi[2], hi[3]);
    }
}

// ---------------- gemm2 + fused tail (L2 RED, counter, per-graph L3/L4) -------
// grid (4, 64, 2) = 512 blocks, 128 threads. All blocks provably co-resident.
// Blocks with x==0,z==0 (64 of them) spin on g_done then run graph y's tail.
__global__ void __launch_bounds__(128) k_gemm2t(
        const float* __restrict__ vb1, const float* __restrict__ ab1,
        const float* __restrict__ vW2, const float* __restrict__ aW2,
        const float* __restrict__ vb2, const float* __restrict__ ab2,
        const float* __restrict__ vW3, const float* __restrict__ vb3,
        const float* __restrict__ aW3, const float* __restrict__ ab3,
        const float* __restrict__ vW4, const float* __restrict__ vb4,
        const float* __restrict__ aW4, const float* __restrict__ ab4,
        float* __restrict__ out) {
    constexpr int KC = 16;
    __shared__ float As[KC * AS_STRIDE];
    __shared__ float Ws[KC * WS_STRIDE];
    __shared__ float h2s[512];
    __shared__ float h3s[128];
    __shared__ float res[9];

    int z  = blockIdx.z;
    const float* Wg = z ? aW2 : vW2;
    const float* bin = z ? ab1 : vb1;
    int k0 = blockIdx.y * KC;
    int j0 = blockIdx.x * 64;
    int tid = threadIdx.x;

    // stage A from h1 with fused bias+relu (KQ = 4)
    {
        int colbase = z * 1024 + k0;
        for (int e = tid; e < 256; e += 128) {
            int r = e >> 2, kq = e & 3;
            float4 v = *(const float4*)(g_h1 + (long)r * 2048 + colbase + kq * 4);
            float4 bb = *(const float4*)(bin + k0 + kq * 4);
            v.x = fmaxf(v.x + bb.x, 0.f);
            v.y = fmaxf(v.y + bb.y, 0.f);
            v.z = fmaxf(v.z + bb.z, 0.f);
            v.w = fmaxf(v.w + bb.w, 0.f);
            As[(kq * 4 + 0) * AS_STRIDE + r] = v.x;
            As[(kq * 4 + 1) * AS_STRIDE + r] = v.y;
            As[(kq * 4 + 2) * AS_STRIDE + r] = v.z;
            As[(kq * 4 + 3) * AS_STRIDE + r] = v.w;
        }
    }
    for (int e = tid; e < KC * 16; e += 128) {
        int kk = e >> 4, jq = e & 15;
        float4 v = *(const float4*)(Wg + (long)(k0 + kk) * 256 + j0 + jq * 4);
        *(float4*)&Ws[kk * WS_STRIDE + jq * 4] = v;
    }
    __syncthreads();

    int r0 = (tid >> 4) * 8;
    int jb = (tid & 15) * 4;

    unsigned long long acc[4][4];
#pragma unroll
    for (int i = 0; i < 4; i++)
#pragma unroll
        for (int j = 0; j < 4; j++) acc[i][j] = 0ull;

#pragma unroll 8
    for (int kk = 0; kk < KC; kk++) {
        F4U a0, a1, w;
        a0.v = *(float4*)&As[kk * AS_STRIDE + r0];
        a1.v = *(float4*)&As[kk * AS_STRIDE + r0 + 4];
        w.v  = *(float4*)&Ws[kk * WS_STRIDE + jb];
        unsigned long long ap[4] = {a0.u[0], a0.u[1], a1.u[0], a1.u[1]};
#pragma unroll
        for (int j = 0; j < 4; j++) {
            unsigned long long wd;
            asm("mov.b64 %0, {%1, %1};" : "=l"(wd) : "f"(w.f[j]));
            asm("fma.rn.f32x2 %0, %1, %2, %0;" : "+l"(acc[0][j]) : "l"(ap[0]), "l"(wd));
            asm("fma.rn.f32x2 %0, %1, %2, %0;" : "+l"(acc[1][j]) : "l"(ap[1]), "l"(wd));
            asm("fma.rn.f32x2 %0, %1, %2, %0;" : "+l"(acc[2][j]) : "l"(ap[2]), "l"(wd));
            asm("fma.rn.f32x2 %0, %1, %2, %0;" : "+l"(acc[3][j]) : "l"(ap[3]), "l"(wd));
        }
    }

    float* obase = g_h2 + z * 256 + j0 + jb;
#pragma unroll
    for (int rp = 0; rp < 4; rp++) {
        float lo[4], hi[4];
#pragma unroll
        for (int j = 0; j < 4; j++)
            asm("mov.b64 {%0, %1}, %2;" : "=f"(lo[j]), "=f"(hi[j]) : "l"(acc[rp][j]));
        red_add_v4(obase + (long)(r0 + 2 * rp)     * 512, lo[0], lo[1], lo[2], lo[3]);
        red_add_v4(obase + (long)(r0 + 2 * rp + 1) * 512, hi[0], hi[1], hi[2], hi[3]);
    }

    // publish completion
    __threadfence();
    __syncthreads();
    if (tid == 0) atomicAdd(&g_done, 1);

    // 64 tail blocks: graph y
    if (blockIdx.x != 0 || blockIdx.z != 0) return;
    if (tid == 0) {
        while (atomicAdd(&g_done, 0) < 512) __nanosleep(64);
        __threadfence();
    }
    __syncthreads();

    int b = blockIdx.y;
    for (int e = tid; e < 512; e += 128) {
        float s = __ldcg(&g_h2[b * 512 + e]) + ((e < 256) ? vb2[e] : ab2[e - 256]);
        h2s[e] = fmaxf(s, 0.f);
    }
    __syncthreads();
    {   // L3: thread tid -> output tid, K=256
        int head = tid >> 6, j = tid & 63;
        const float* W3 = head ? aW3 : vW3;
        const float* hh = h2s + head * 256;
        float s = 0.f;
#pragma unroll 8
        for (int kq = 0; kq < 256; kq++) s = fmaf(hh[kq], W3[kq * 64 + j], s);
        s += head ? ab3[j] : vb3[j];
        h3s[tid] = fmaxf(s, 0.f);
    }
    __syncthreads();
    if (tid < 9) {
        const float* hrow = &h3s[(tid == 0) ? 0 : 64];
        float s = (tid == 0) ? vb4[0] : ab4[tid - 1];
        if (tid == 0) {
#pragma unroll 8
            for (int c = 0; c < 64; c++) s = fmaf(hrow[c], vW4[c], s);
        } else {
#pragma unroll 8
            for (int c = 0; c < 64; c++) s = fmaf(hrow[c], aW4[c * A_DIM + (tid - 1)], s);
        }
        res[tid] = s;
    }
    __syncthreads();
    if (tid < 8) {
        float m = 0.f;
#pragma unroll
        for (int q = 1; q < 9; q++) m += res[q];
        m *= 0.125f;
        out[b * A_DIM + tid] = res[0] + res[1 + tid] - m;
    }
}

// ---------------- launch ----------------
extern "C" void kernel_launch(void* const* d_in, const int* in_sizes, int n_in,
                              void* d_out, int out_size) {
    const float* x       = (const float*)d_in[0];
    const int*   ei      = (const int*)  d_in[1];
    const int*   tls     = (const int*)  d_in[2];
    const float* W       = (const float*)d_in[3];
    const float* att_src = (const float*)d_in[4];
    const float* att_dst = (const float*)d_in[5];
    const float* b_gat   = (const float*)d_in[6];
    const float* vW1 = (const float*)d_in[7];  const float* vb1 = (const float*)d_in[8];
    const float* vW2 = (const float*)d_in[9];  const float* vb2 = (const float*)d_in[10];
    const float* vW3 = (const float*)d_in[11]; const float* vb3 = (const float*)d_in[12];
    const float* vW4 = (const float*)d_in[13]; const float* vb4 = (const float*)d_in[14];
    const float* aW1 = (const float*)d_in[15]; const float* ab1 = (const float*)d_in[16];
    const float* aW2 = (const float*)d_in[17]; const float* ab2 = (const float*)d_in[18];
    const float* aW3 = (const float*)d_in[19]; const float* ab3 = (const float*)d_in[20];
    const float* aW4 = (const float*)d_in[21]; const float* ab4 = (const float*)d_in[22];

    float* h1 = nullptr; float* ft = nullptr;
    cudaGetSymbolAddress((void**)&h1, g_h1);
    cudaGetSymbolAddress((void**)&ft, g_feats);

    k_pre<<<2420, 256>>>(x, W, att_src, att_dst, ei, tls, vW1, aW1, vW2, aW2, vW3, aW3);
    k_agg<<<NSLOTS, 256>>>(x, W, tls, b_gat);

    // L1: feats[64,1024] @ {vW1,aW1}[1024,1024] -> RED h1. KC=16, 2048 blocks.
    k_gemm<16><<<dim3(16, 64, 2), 128>>>(ft, 0, 1024, 0, nullptr, nullptr, vW1, aW1, h1, 1024);
    // L2 + fused tail: 512 blocks, all co-resident; 64 tail blocks finish the net.
    k_gemm2t<<<dim3(4, 64, 2), 128>>>(vb1, ab1, vW2, aW2, vb2, ab2,
                                      vW3, vb3, aW3, ab3, vW4, vb4, aW4, ab4,
                                      (float*)d_out);
}

// round 16
// speedup vs baseline: 1.0819x; 1.0819x over previous
#include <cuda_runtime.h>
#include <cstdint>
#include <math_constants.h>

#define N_NODES 32768
#define N_PER   512
#define BGRAPH  64
#define E_EDGES 524288
#define C_IN    32
#define HDIM    128
#define KTLS    8
#define A_DIM   8
#define NSLOTS  512
#define ECAP    1024

// ---------------- scratch (device globals; no allocs allowed) ----------------
__device__ float g_as[N_NODES];
__device__ float g_ad[N_NODES];
__device__ int   g_cur[NSLOTS];          // zero-init at load; k_agg re-zeros
__device__ int   g_srcs[NSLOTS * ECAP];
__device__ __align__(16) float g_feats[BGRAPH * 1024];
__device__ __align__(16) float g_h1[BGRAPH * 2048];   // RED-accumulated, pre-bias
__device__ __align__(16) float g_h2[BGRAPH * 512];

union F4U { float4 v; unsigned long long u[2]; float f[4]; };

__device__ __forceinline__ void red_add_v4(float* addr, float a, float b, float c, float d) {
    asm volatile("red.global.add.v4.f32 [%0], {%1,%2,%3,%4};"
                 :: "l"(addr), "f"(a), "f"(b), "f"(c), "f"(d) : "memory");
}

// ---------------- fused prefetch + att + edge-filter + zero kernel ------------
// blocks [0,82): L2-prefetch weights (incl. W3); [82,210): att scalars;
// [210,2260): edge filter; [2260,2420): zero h1/h2
__global__ void k_pre(const float* __restrict__ x, const float* __restrict__ W,
                      const float* __restrict__ att_src, const float* __restrict__ att_dst,
                      const int* __restrict__ ei, const int* __restrict__ tls,
                      const float* __restrict__ vW1, const float* __restrict__ aW1,
                      const float* __restrict__ vW2, const float* __restrict__ aW2,
                      const float* __restrict__ vW3, const float* __restrict__ aW3) {
    __shared__ float ws[C_IN], wd[C_IN];
    __shared__ int tl[KTLS];
    __shared__ unsigned bm[16];          // 512-bit membership bitmap over local idx
    int t = threadIdx.x;
    if (blockIdx.x < 82) {
        // prefetch weights into L2: 82944 lines of 128B, 4 per thread
        int base = (blockIdx.x * 256 + t) * 4;
#pragma unroll
        for (int q = 0; q < 4; q++) {
            int L = base + q;
            if (L < 82944) {
                const float* p;
                if (L < 32768)      p = vW1 + (long)L * 32;
                else if (L < 65536) p = aW1 + (long)(L - 32768) * 32;
                else if (L < 73728) p = vW2 + (long)(L - 65536) * 32;
                else if (L < 81920) p = aW2 + (long)(L - 73728) * 32;
                else if (L < 82432) p = vW3 + (long)(L - 81920) * 32;
                else                p = aW3 + (long)(L - 82432) * 32;
                asm volatile("prefetch.global.L2 [%0];" :: "l"(p));
            }
        }
    } else if (blockIdx.x < 210) {
        if (t < 64) {
            int c = t & 31;
            const float* av = (t < 32) ? att_src : att_dst;
            float s = 0.f;
#pragma unroll 8
            for (int d = 0; d < HDIM; d++) s = fmaf(W[c * HDIM + d], av[d], s);
            if (t < 32) ws[c] = s; else wd[c] = s;
        }
        __syncthreads();
        int n = (blockIdx.x - 82) * 256 + t;
        const float4* xr = (const float4*)(x + n * C_IN);
        float s1 = 0.f, s2 = 0.f;
#pragma unroll
        for (int q = 0; q < 8; q++) {
            float4 v = xr[q];
            s1 = fmaf(v.x, ws[q*4+0], s1); s2 = fmaf(v.x, wd[q*4+0], s2);
            s1 = fmaf(v.y, ws[q*4+1], s1); s2 = fmaf(v.y, wd[q*4+1], s2);
            s1 = fmaf(v.z, ws[q*4+2], s1); s2 = fmaf(v.z, wd[q*4+2], s2);
            s1 = fmaf(v.w, ws[q*4+3], s1); s2 = fmaf(v.w, wd[q*4+3], s2);
        }
        g_as[n] = s1;
        g_ad[n] = s2;
    } else if (blockIdx.x < 2260) {
        if (t < 16) bm[t] = 0u;
        if (t < KTLS) tl[t] = tls[t];
        __syncthreads();
        if (t < KTLS) atomicOr(&bm[tl[t] >> 5], 1u << (tl[t] & 31));
        __syncthreads();
        long i = (long)(blockIdx.x - 210) * 256 + t;     // < 524800 exactly
        if (i < E_EDGES) {
            int d = ei[E_EDGES + i];
            int loc = d & (N_PER - 1);
            if ((bm[loc >> 5] >> (loc & 31)) & 1u) {      // ~1.7% hit rate
                int b = d >> 9;
                int s = ei[i];
#pragma unroll
                for (int k = 0; k < KTLS; k++) {
                    if (tl[k] == loc) {
                        int slot = b * KTLS + k;
                        int p = atomicAdd(&g_cur[slot], 1);
                        if (p < ECAP) g_srcs[slot * ECAP + p] = s;
                    }
                }
            }
        } else {                                          // self loops
            int slot = (int)(i - E_EDGES);
            int b = slot >> 3, k = slot & 7;
            int n = b * N_PER + tl[k];
            int p = atomicAdd(&g_cur[slot], 1);
            if (p < ECAP) g_srcs[slot * ECAP + p] = n;
        }
    } else {
        int i = (blockIdx.x - 2260) * 256 + t;            // < 40960 float4s
        float4 z = make_float4(0.f, 0.f, 0.f, 0.f);
        if (i < 32768)        ((float4*)g_h1)[i] = z;
        else if (i < 40960)   ((float4*)g_h2)[i - 32768] = z;
    }
}

// ---------------- per-target softmax + aggregation -> feats (256 thr) --------
__global__ void __launch_bounds__(256) k_agg(
        const float* __restrict__ x, const float* __restrict__ W,
        const int* __restrict__ tls, const float* __restrict__ b_gat) {
    __shared__ float Ws[C_IN * HDIM];      // 16 KB
    __shared__ float e_s[ECAP];            // 4 KB
    __shared__ int   s_s[ECAP];            // 4 KB
    __shared__ float racc[8][HDIM];        // 4 KB
    __shared__ float rden[8];
    __shared__ float red8[8];
    __shared__ float m_sh;

    int slot = blockIdx.x;
    int b = slot >> 3, k = slot & 7;
    int t = threadIdx.x;
    int w = t >> 5, l = t & 31;
    int n = b * N_PER + tls[k];
    float ad_n = g_ad[n];
    int deg = g_cur[slot];
    if (deg > ECAP) deg = ECAP;

    {
        const float4* Wg = (const float4*)W;
        float4* Wl = (float4*)Ws;
        for (int u = t; u < C_IN * HDIM / 4; u += 256) Wl[u] = Wg[u];
    }

    float lmax = -CUDART_INF_F;
    for (int j = t; j < deg; j += 256) {
        int s = g_srcs[slot * ECAP + j];
        float e = g_as[s] + ad_n;
        e = e > 0.f ? e : 0.2f * e;
        e_s[j] = e;
        s_s[j] = s;
        lmax = fmaxf(lmax, e);
    }
#pragma unroll
    for (int off = 16; off; off >>= 1)
        lmax = fmaxf(lmax, __shfl_xor_sync(0xFFFFFFFFu, lmax, off));
    if (l == 0) red8[w] = lmax;
    __syncthreads();
    if (t == 0) {
        float m0 = fmaxf(fmaxf(red8[0], red8[1]), fmaxf(red8[2], red8[3]));
        float m1 = fmaxf(fmaxf(red8[4], red8[5]), fmaxf(red8[6], red8[7]));
        m_sh = fmaxf(m0, m1);
    }
    __syncthreads();
    float m = m_sh;

    float4 acc = make_float4(0.f, 0.f, 0.f, 0.f);
    float den = 0.f;
    const float4* Ws4 = (const float4*)Ws;
    for (int j = w; j < deg; j += 8) {
        int s = s_s[j];
        float ex = __expf(e_s[j] - m);
        den += ex;
        float xv = x[s * C_IN + l];
        float4 h = make_float4(0.f, 0.f, 0.f, 0.f);
#pragma unroll
        for (int c = 0; c < C_IN; c++) {
            float xc = __shfl_sync(0xFFFFFFFFu, xv, c);
            float4 wv = Ws4[c * 32 + l];
            h.x = fmaf(xc, wv.x, h.x);
            h.y = fmaf(xc, wv.y, h.y);
            h.z = fmaf(xc, wv.z, h.z);
            h.w = fmaf(xc, wv.w, h.w);
        }
        acc.x = fmaf(ex, h.x, acc.x);
        acc.y = fmaf(ex, h.y, acc.y);
        acc.z = fmaf(ex, h.z, acc.z);
        acc.w = fmaf(ex, h.w, acc.w);
    }
    *((float4*)&racc[w][4 * l]) = acc;
    if (l == 0) rden[w] = den;
    __syncthreads();

    if (t < HDIM) {
        float tot = ((racc[0][t] + racc[1][t]) + (racc[2][t] + racc[3][t]))
                  + ((racc[4][t] + racc[5][t]) + (racc[6][t] + racc[7][t]));
        float dtot = ((rden[0] + rden[1]) + (rden[2] + rden[3]))
                   + ((rden[4] + rden[5]) + (rden[6] + rden[7]));
        float v = tot / (dtot + 1e-16f) + b_gat[t];
        v = v > 0.f ? v : expm1f(v);
        g_feats[b * (KTLS * HDIM) + k * HDIM + t] = v;
    }
    if (t == 0) g_cur[slot] = 0;       // reset cursor for next graph replay
}

// ---------------- split-K SGEMM, RED accumulation into pre-zeroed output ------
// Block tile: 64 rows x 64 cols x KC. 128 threads, thread tile 8x4 (f32x2 row pairs).
#define AS_STRIDE 68
#define WS_STRIDE 68

template <int KC>
__global__ void __launch_bounds__(128) k_gemm(
        const float* __restrict__ Ain, int fuse, int ldin, int zstride,
        const float* __restrict__ bv_in, const float* __restrict__ ba_in,
        const float* __restrict__ Wv, const float* __restrict__ Wa,
        float* __restrict__ O, int Nhead) {
    __shared__ float As[KC * AS_STRIDE];
    __shared__ float Ws[KC * WS_STRIDE];

    int z  = blockIdx.z;
    const float* Wg = z ? Wa : Wv;
    int k0 = blockIdx.y * KC;
    int j0 = blockIdx.x * 64;
    int tid = threadIdx.x;

    // stage A chunk (64 rows x KC), transposed As[k][row]
    {
        constexpr int KQ = KC / 4;
        int colbase = z * zstride + k0;
        const float* bin = z ? ba_in : bv_in;
        for (int e = tid; e < 64 * KQ; e += 128) {
            int r = e / KQ, kq = e % KQ;
            float4 v = *(const float4*)(Ain + (long)r * ldin + colbase + kq * 4);
            if (fuse) {
                float4 bb = *(const float4*)(bin + k0 + kq * 4);
                v.x = fmaxf(v.x + bb.x, 0.f);
                v.y = fmaxf(v.y + bb.y, 0.f);
                v.z = fmaxf(v.z + bb.z, 0.f);
                v.w = fmaxf(v.w + bb.w, 0.f);
            }
            As[(kq * 4 + 0) * AS_STRIDE + r] = v.x;
            As[(kq * 4 + 1) * AS_STRIDE + r] = v.y;
            As[(kq * 4 + 2) * AS_STRIDE + r] = v.z;
            As[(kq * 4 + 3) * AS_STRIDE + r] = v.w;
        }
    }
    // stage W chunk (KC rows x 64 cols)
    for (int e = tid; e < KC * 16; e += 128) {
        int kk = e >> 4, jq = e & 15;
        float4 v = *(const float4*)(Wg + (long)(k0 + kk) * Nhead + j0 + jq * 4);
        *(float4*)&Ws[kk * WS_STRIDE + jq * 4] = v;
    }
    __syncthreads();

    int r0 = (tid >> 4) * 8;      // 8 row-groups
    int jb = (tid & 15) * 4;      // 16 col-groups of 4

    unsigned long long acc[4][4];
#pragma unroll
    for (int i = 0; i < 4; i++)
#pragma unroll
        for (int j = 0; j < 4; j++) acc[i][j] = 0ull;

#pragma unroll 8
    for (int kk = 0; kk < KC; kk++) {
        F4U a0, a1, w;
        a0.v = *(float4*)&As[kk * AS_STRIDE + r0];
        a1.v = *(float4*)&As[kk * AS_STRIDE + r0 + 4];
        w.v  = *(float4*)&Ws[kk * WS_STRIDE + jb];
        unsigned long long ap[4] = {a0.u[0], a0.u[1], a1.u[0], a1.u[1]};
#pragma unroll
        for (int j = 0; j < 4; j++) {
            unsigned long long wd;
            asm("mov.b64 %0, {%1, %1};" : "=l"(wd) : "f"(w.f[j]));
            asm("fma.rn.f32x2 %0, %1, %2, %0;" : "+l"(acc[0][j]) : "l"(ap[0]), "l"(wd));
            asm("fma.rn.f32x2 %0, %1, %2, %0;" : "+l"(acc[1][j]) : "l"(ap[1]), "l"(wd));
            asm("fma.rn.f32x2 %0, %1, %2, %0;" : "+l"(acc[2][j]) : "l"(ap[2]), "l"(wd));
            asm("fma.rn.f32x2 %0, %1, %2, %0;" : "+l"(acc[3][j]) : "l"(ap[3]), "l"(wd));
        }
    }

    int ntot = 2 * Nhead;
    float* obase = O + z * Nhead + j0 + jb;
#pragma unroll
    for (int rp = 0; rp < 4; rp++) {
        float lo[4], hi[4];
#pragma unroll
        for (int j = 0; j < 4; j++)
            asm("mov.b64 {%0, %1}, %2;" : "=f"(lo[j]), "=f"(hi[j]) : "l"(acc[rp][j]));
        red_add_v4(obase + (long)(r0 + 2 * rp)     * ntot, lo[0], lo[1], lo[2], lo[3]);
        red_add_v4(obase + (long)(r0 + 2 * rp + 1) * ntot, hi[0], hi[1], hi[2], hi[3]);
    }
}

// ---------------- per-graph tail: L2-epilogue + L3 + L4 + dueling combine -----
// 64 blocks (one per graph) x 512 threads.
__global__ void __launch_bounds__(512) k_tail(
        const float* __restrict__ vb2, const float* __restrict__ ab2,
        const float* __restrict__ vW3, const float* __restrict__ vb3,
        const float* __restrict__ aW3, const float* __restrict__ ab3,
        const float* __restrict__ vW4, const float* __restrict__ vb4,
        const float* __restrict__ aW4, const float* __restrict__ ab4,
        float* __restrict__ out) {
    __shared__ float h2s[512];
    __shared__ float part[128][4];
    __shared__ float h3s[128];
    __shared__ float res[9];
    int b = blockIdx.x;
    int t = threadIdx.x;

    // L2 epilogue: relu(h2_raw + bias), one element per thread
    {
        float s = g_h2[b * 512 + t] + ((t < 256) ? vb2[t] : ab2[t - 256]);
        h2s[t] = fmaxf(s, 0.f);
    }
    __syncthreads();

    // L3: 128 outputs, K=256 split into four quarters
    {
        int o = t & 127;          // output index
        int quar = t >> 7;        // K quarter (0..3)
        int head = o >> 6, j = o & 63;
        const float* W3 = head ? aW3 : vW3;
        const float* hh = h2s + head * 256 + quar * 64;
        const float* wp = W3 + (quar * 64) * 64 + j;
        float s = 0.f;
#pragma unroll 8
        for (int kq = 0; kq < 64; kq++) s = fmaf(hh[kq], wp[kq * 64], s);
        part[o][quar] = s;
    }
    __syncthreads();
    if (t < 128) {
        int head = t >> 6, j = t & 63;
        float s = (part[t][0] + part[t][1]) + (part[t][2] + part[t][3])
                + (head ? ab3[j] : vb3[j]);
        h3s[t] = fmaxf(s, 0.f);
    }
    __syncthreads();

    // L4: 9 dots of length 64
    if (t < 9) {
        const float* hrow = &h3s[(t == 0) ? 0 : 64];
        float s = (t == 0) ? vb4[0] : ab4[t - 1];
        if (t == 0) {
#pragma unroll 8
            for (int c = 0; c < 64; c++) s = fmaf(hrow[c], vW4[c], s);
        } else {
#pragma unroll 8
            for (int c = 0; c < 64; c++) s = fmaf(hrow[c], aW4[c * A_DIM + (t - 1)], s);
        }
        res[t] = s;
    }
    __syncthreads();
    if (t < 8) {
        float m = 0.f;
#pragma unroll
        for (int q = 1; q < 9; q++) m += res[q];
        m *= 0.125f;
        out[b * A_DIM + t] = res[0] + res[1 + t] - m;
    }
}

// ---------------- launch ----------------
extern "C" void kernel_launch(void* const* d_in, const int* in_sizes, int n_in,
                              void* d_out, int out_size) {
    const float* x       = (const float*)d_in[0];
    const int*   ei      = (const int*)  d_in[1];
    const int*   tls     = (const int*)  d_in[2];
    const float* W       = (const float*)d_in[3];
    const float* att_src = (const float*)d_in[4];
    const float* att_dst = (const float*)d_in[5];
    const float* b_gat   = (const float*)d_in[6];
    const float* vW1 = (const float*)d_in[7];  const float* vb1 = (const float*)d_in[8];
    const float* vW2 = (const float*)d_in[9];  const float* vb2 = (const float*)d_in[10];
    const float* vW3 = (const float*)d_in[11]; const float* vb3 = (const float*)d_in[12];
    const float* vW4 = (const float*)d_in[13]; const float* vb4 = (const float*)d_in[14];
    const float* aW1 = (const float*)d_in[15]; const float* ab1 = (const float*)d_in[16];
    const float* aW2 = (const float*)d_in[17]; const float* ab2 = (const float*)d_in[18];
    const float* aW3 = (const float*)d_in[19]; const float* ab3 = (const float*)d_in[20];
    const float* aW4 = (const float*)d_in[21]; const float* ab4 = (const float*)d_in[22];

    float* h1 = nullptr; float* h2 = nullptr; float* ft = nullptr;
    cudaGetSymbolAddress((void**)&h1, g_h1);
    cudaGetSymbolAddress((void**)&h2, g_h2);
    cudaGetSymbolAddress((void**)&ft, g_feats);

    k_pre<<<2420, 256>>>(x, W, att_src, att_dst, ei, tls, vW1, aW1, vW2, aW2, vW3, aW3);
    k_agg<<<NSLOTS, 256>>>(x, W, tls, b_gat);

    // L1: feats[64,1024] @ {vW1,aW1}[1024,1024] -> RED h1 (raw). KC=16, 2048 blocks.
    k_gemm<16><<<dim3(16, 64, 2), 128>>>(ft, 0, 1024, 0, nullptr, nullptr, vW1, aW1, h1, 1024);
    // L2: relu(h1+b1)[64,1024/head] @ {vW2,aW2}[1024,256] -> RED h2. KC=8, 1024 blocks.
    k_gemm<8><<<dim3(4, 128, 2), 128>>>(h1, 1, 2048, 1024, vb1, ab1, vW2, aW2, h2, 256);
    // L2-epilogue + L3 + L4 + combine, per graph
    k_tail<<<BGRAPH, 512>>>(vb2, ab2, vW3, vb3, aW3, ab3, vW4, vb4, aW4, ab4, (float*)d_out);
}

// round 17
// speedup vs baseline: 1.1220x; 1.0371x over previous
#include <cuda_runtime.h>
#include <cstdint>
#include <math_constants.h>

#define N_NODES 32768
#define N_PER   512
#define BGRAPH  64
#define E_EDGES 524288
#define C_IN    32
#define HDIM    128
#define KTLS    8
#define A_DIM   8
#define NSLOTS  512
#define ECAP    1024

// ---------------- scratch (device globals; no allocs allowed) ----------------
__device__ float g_as[N_NODES];
__device__ float g_ad[N_NODES];
__device__ int   g_cur[NSLOTS];          // zero-init at load; k_agg re-zeros
__device__ int   g_srcs[NSLOTS * ECAP];
__device__ __align__(16) float g_feats[BGRAPH * 1024];
__device__ __align__(16) float g_h1[BGRAPH * 2048];   // RED-accumulated, pre-bias
__device__ __align__(16) float g_h2[BGRAPH * 512];

union F4U { float4 v; unsigned long long u[2]; float f[4]; };

__device__ __forceinline__ void red_add_v4(float* addr, float a, float b, float c, float d) {
    asm volatile("red.global.add.v4.f32 [%0], {%1,%2,%3,%4};"
                 :: "l"(addr), "f"(a), "f"(b), "f"(c), "f"(d) : "memory");
}

// ---------------- fused prefetch + att + edge-filter + zero kernel ------------
// blocks [0,82): L2-prefetch weights (incl. W3); [82,210): att scalars;
// [210,2260): edge filter; [2260,2420): zero h1/h2
__global__ void k_pre(const float* __restrict__ x, const float* __restrict__ W,
                      const float* __restrict__ att_src, const float* __restrict__ att_dst,
                      const int* __restrict__ ei, const int* __restrict__ tls,
                      const float* __restrict__ vW1, const float* __restrict__ aW1,
                      const float* __restrict__ vW2, const float* __restrict__ aW2,
                      const float* __restrict__ vW3, const float* __restrict__ aW3) {
    __shared__ float ws[C_IN], wd[C_IN];
    __shared__ int tl[KTLS];
    __shared__ unsigned bm[16];          // 512-bit membership bitmap over local idx
    int t = threadIdx.x;
    if (blockIdx.x < 82) {
        // prefetch weights into L2: 82944 lines of 128B, 4 per thread
        int base = (blockIdx.x * 256 + t) * 4;
#pragma unroll
        for (int q = 0; q < 4; q++) {
            int L = base + q;
            if (L < 82944) {
                const float* p;
                if (L < 32768)      p = vW1 + (long)L * 32;
                else if (L < 65536) p = aW1 + (long)(L - 32768) * 32;
                else if (L < 73728) p = vW2 + (long)(L - 65536) * 32;
                else if (L < 81920) p = aW2 + (long)(L - 73728) * 32;
                else if (L < 82432) p = vW3 + (long)(L - 81920) * 32;
                else                p = aW3 + (long)(L - 82432) * 32;
                asm volatile("prefetch.global.L2 [%0];" :: "l"(p));
            }
        }
    } else if (blockIdx.x < 210) {
        if (t < 64) {
            int c = t & 31;
            const float* av = (t < 32) ? att_src : att_dst;
            float s = 0.f;
#pragma unroll 8
            for (int d = 0; d < HDIM; d++) s = fmaf(W[c * HDIM + d], av[d], s);
            if (t < 32) ws[c] = s; else wd[c] = s;
        }
        __syncthreads();
        int n = (blockIdx.x - 82) * 256 + t;
        const float4* xr = (const float4*)(x + n * C_IN);
        float s1 = 0.f, s2 = 0.f;
#pragma unroll
        for (int q = 0; q < 8; q++) {
            float4 v = xr[q];
            s1 = fmaf(v.x, ws[q*4+0], s1); s2 = fmaf(v.x, wd[q*4+0], s2);
            s1 = fmaf(v.y, ws[q*4+1], s1); s2 = fmaf(v.y, wd[q*4+1], s2);
            s1 = fmaf(v.z, ws[q*4+2], s1); s2 = fmaf(v.z, wd[q*4+2], s2);
            s1 = fmaf(v.w, ws[q*4+3], s1); s2 = fmaf(v.w, wd[q*4+3], s2);
        }
        g_as[n] = s1;
        g_ad[n] = s2;
    } else if (blockIdx.x < 2260) {
        if (t < 16) bm[t] = 0u;
        if (t < KTLS) tl[t] = tls[t];
        __syncthreads();
        if (t < KTLS) atomicOr(&bm[tl[t] >> 5], 1u << (tl[t] & 31));
        __syncthreads();
        long i = (long)(blockIdx.x - 210) * 256 + t;     // < 524800 exactly
        if (i < E_EDGES) {
            int d = ei[E_EDGES + i];
            int loc = d & (N_PER - 1);
            if ((bm[loc >> 5] >> (loc & 31)) & 1u) {      // ~1.7% hit rate
                int b = d >> 9;
                int s = ei[i];
#pragma unroll
                for (int k = 0; k < KTLS; k++) {
                    if (tl[k] == loc) {
                        int slot = b * KTLS + k;
                        int p = atomicAdd(&g_cur[slot], 1);
                        if (p < ECAP) g_srcs[slot * ECAP + p] = s;
                    }
                }
            }
        } else {                                          // self loops
            int slot = (int)(i - E_EDGES);
            int b = slot >> 3, k = slot & 7;
            int n = b * N_PER + tl[k];
            int p = atomicAdd(&g_cur[slot], 1);
            if (p < ECAP) g_srcs[slot * ECAP + p] = n;
        }
    } else {
        int i = (blockIdx.x - 2260) * 256 + t;            // < 40960 float4s
        float4 z = make_float4(0.f, 0.f, 0.f, 0.f);
        if (i < 32768)        ((float4*)g_h1)[i] = z;
        else if (i < 40960)   ((float4*)g_h2)[i - 32768] = z;
    }
}

// ---------------- per-target softmax + aggregation -> feats (256 thr) --------
__global__ void __launch_bounds__(256) k_agg(
        const float* __restrict__ x, const float* __restrict__ W,
        const int* __restrict__ tls, const float* __restrict__ b_gat) {
    __shared__ float Ws[C_IN * HDIM];      // 16 KB
    __shared__ float e_s[ECAP];            // 4 KB
    __shared__ int   s_s[ECAP];            // 4 KB
    __shared__ float racc[8][HDIM];        // 4 KB
    __shared__ float rden[8];
    __shared__ float red8[8];
    __shared__ float m_sh;

    int slot = blockIdx.x;
    int b = slot >> 3, k = slot & 7;
    int t = threadIdx.x;
    int w = t >> 5, l = t & 31;
    int n = b * N_PER + tls[k];
    float ad_n = g_ad[n];
    int deg = g_cur[slot];
    if (deg > ECAP) deg = ECAP;

    {
        const float4* Wg = (const float4*)W;
        float4* Wl = (float4*)Ws;
        for (int u = t; u < C_IN * HDIM / 4; u += 256) Wl[u] = Wg[u];
    }

    float lmax = -CUDART_INF_F;
    for (int j = t; j < deg; j += 256) {
        int s = g_srcs[slot * ECAP + j];
        float e = g_as[s] + ad_n;
        e = e > 0.f ? e : 0.2f * e;
        e_s[j] = e;
        s_s[j] = s;
        lmax = fmaxf(lmax, e);
    }
#pragma unroll
    for (int off = 16; off; off >>= 1)
        lmax = fmaxf(lmax, __shfl_xor_sync(0xFFFFFFFFu, lmax, off));
    if (l == 0) red8[w] = lmax;
    __syncthreads();
    if (t == 0) {
        float m0 = fmaxf(fmaxf(red8[0], red8[1]), fmaxf(red8[2], red8[3]));
        float m1 = fmaxf(fmaxf(red8[4], red8[5]), fmaxf(red8[6], red8[7]));
        m_sh = fmaxf(m0, m1);
    }
    __syncthreads();
    float m = m_sh;

    float4 acc = make_float4(0.f, 0.f, 0.f, 0.f);
    float den = 0.f;
    const float4* Ws4 = (const float4*)Ws;
    for (int j = w; j < deg; j += 8) {
        int s = s_s[j];
        float ex = __expf(e_s[j] - m);
        den += ex;
        float xv = x[s * C_IN + l];
        float4 h = make_float4(0.f, 0.f, 0.f, 0.f);
#pragma unroll
        for (int c = 0; c < C_IN; c++) {
            float xc = __shfl_sync(0xFFFFFFFFu, xv, c);
            float4 wv = Ws4[c * 32 + l];
            h.x = fmaf(xc, wv.x, h.x);
            h.y = fmaf(xc, wv.y, h.y);
            h.z = fmaf(xc, wv.z, h.z);
            h.w = fmaf(xc, wv.w, h.w);
        }
        acc.x = fmaf(ex, h.x, acc.x);
        acc.y = fmaf(ex, h.y, acc.y);
        acc.z = fmaf(ex, h.z, acc.z);
        acc.w = fmaf(ex, h.w, acc.w);
    }
    *((float4*)&racc[w][4 * l]) = acc;
    if (l == 0) rden[w] = den;
    __syncthreads();

    if (t < HDIM) {
        float tot = ((racc[0][t] + racc[1][t]) + (racc[2][t] + racc[3][t]))
                  + ((racc[4][t] + racc[5][t]) + (racc[6][t] + racc[7][t]));
        float dtot = ((rden[0] + rden[1]) + (rden[2] + rden[3]))
                   + ((rden[4] + rden[5]) + (rden[6] + rden[7]));
        float v = tot / (dtot + 1e-16f) + b_gat[t];
        v = v > 0.f ? v : expm1f(v);
        g_feats[b * (KTLS * HDIM) + k * HDIM + t] = v;
    }
    if (t == 0) g_cur[slot] = 0;       // reset cursor for next graph replay
}

// ---------------- split-K SGEMM, RED accumulation into pre-zeroed output ------
// Block tile: 64 rows x 64 cols x KC. 128 threads, thread tile 8x4 (f32x2 row pairs).
#define AS_STRIDE 68
#define WS_STRIDE 68

template <int KC>
__global__ void __launch_bounds__(128) k_gemm(
        const float* __restrict__ Ain, int fuse, int ldin, int zstride,
        const float* __restrict__ bv_in, const float* __restrict__ ba_in,
        const float* __restrict__ Wv, const float* __restrict__ Wa,
        float* __restrict__ O, int Nhead) {
    __shared__ float As[KC * AS_STRIDE];
    __shared__ float Ws[KC * WS_STRIDE];

    int z  = blockIdx.z;
    const float* Wg = z ? Wa : Wv;
    int k0 = blockIdx.y * KC;
    int j0 = blockIdx.x * 64;
    int tid = threadIdx.x;

    // stage A chunk (64 rows x KC), transposed As[k][row]
    {
        constexpr int KQ = KC / 4;
        int colbase = z * zstride + k0;
        const float* bin = z ? ba_in : bv_in;
        for (int e = tid; e < 64 * KQ; e += 128) {
            int r = e / KQ, kq = e % KQ;
            float4 v = *(const float4*)(Ain + (long)r * ldin + colbase + kq * 4);
            if (fuse) {
                float4 bb = *(const float4*)(bin + k0 + kq * 4);
                v.x = fmaxf(v.x + bb.x, 0.f);
                v.y = fmaxf(v.y + bb.y, 0.f);
                v.z = fmaxf(v.z + bb.z, 0.f);
                v.w = fmaxf(v.w + bb.w, 0.f);
            }
            As[(kq * 4 + 0) * AS_STRIDE + r] = v.x;
            As[(kq * 4 + 1) * AS_STRIDE + r] = v.y;
            As[(kq * 4 + 2) * AS_STRIDE + r] = v.z;
            As[(kq * 4 + 3) * AS_STRIDE + r] = v.w;
        }
    }
    // stage W chunk (KC rows x 64 cols)
    for (int e = tid; e < KC * 16; e += 128) {
        int kk = e >> 4, jq = e & 15;
        float4 v = *(const float4*)(Wg + (long)(k0 + kk) * Nhead + j0 + jq * 4);
        *(float4*)&Ws[kk * WS_STRIDE + jq * 4] = v;
    }
    __syncthreads();

    int r0 = (tid >> 4) * 8;      // 8 row-groups
    int jb = (tid & 15) * 4;      // 16 col-groups of 4

    unsigned long long acc[4][4];
#pragma unroll
    for (int i = 0; i < 4; i++)
#pragma unroll
        for (int j = 0; j < 4; j++) acc[i][j] = 0ull;

#pragma unroll 8
    for (int kk = 0; kk < KC; kk++) {
        F4U a0, a1, w;
        a0.v = *(float4*)&As[kk * AS_STRIDE + r0];
        a1.v = *(float4*)&As[kk * AS_STRIDE + r0 + 4];
        w.v  = *(float4*)&Ws[kk * WS_STRIDE + jb];
        unsigned long long ap[4] = {a0.u[0], a0.u[1], a1.u[0], a1.u[1]};
#pragma unroll
        for (int j = 0; j < 4; j++) {
            unsigned long long wd;
            asm("mov.b64 %0, {%1, %1};" : "=l"(wd) : "f"(w.f[j]));
            asm("fma.rn.f32x2 %0, %1, %2, %0;" : "+l"(acc[0][j]) : "l"(ap[0]), "l"(wd));
            asm("fma.rn.f32x2 %0, %1, %2, %0;" : "+l"(acc[1][j]) : "l"(ap[1]), "l"(wd));
            asm("fma.rn.f32x2 %0, %1, %2, %0;" : "+l"(acc[2][j]) : "l"(ap[2]), "l"(wd));
            asm("fma.rn.f32x2 %0, %1, %2, %0;" : "+l"(acc[3][j]) : "l"(ap[3]), "l"(wd));
        }
    }

    int ntot = 2 * Nhead;
    float* obase = O + z * Nhead + j0 + jb;
#pragma unroll
    for (int rp = 0; rp < 4; rp++) {
        float lo[4], hi[4];
#pragma unroll
        for (int j = 0; j < 4; j++)
            asm("mov.b64 {%0, %1}, %2;" : "=f"(lo[j]), "=f"(hi[j]) : "l"(acc[rp][j]));
        red_add_v4(obase + (long)(r0 + 2 * rp)     * ntot, lo[0], lo[1], lo[2], lo[3]);
        red_add_v4(obase + (long)(r0 + 2 * rp + 1) * ntot, hi[0], hi[1], hi[2], hi[3]);
    }
}

// ---------------- per-graph tail: L2-epilogue + L3 + L4 + dueling combine -----
// 64 blocks (one per graph) x 512 threads.
__global__ void __launch_bounds__(512) k_tail(
        const float* __restrict__ vb2, const float* __restrict__ ab2,
        const float* __restrict__ vW3, const float* __restrict__ vb3,
        const float* __restrict__ aW3, const float* __restrict__ ab3,
        const float* __restrict__ vW4, const float* __restrict__ vb4,
        const float* __restrict__ aW4, const float* __restrict__ ab4,
        float* __restrict__ out) {
    __shared__ float h2s[512];
    __shared__ float part[128][4];
    __shared__ float h3s[128];
    __shared__ float res[9];
    int b = blockIdx.x;
    int t = threadIdx.x;

    // L2 epilogue: relu(h2_raw + bias), one element per thread
    {
        float s = g_h2[b * 512 + t] + ((t < 256) ? vb2[t] : ab2[t - 256]);
        h2s[t] = fmaxf(s, 0.f);
    }
    __syncthreads();

    // L3: 128 outputs, K=256 split into four quarters
    {
        int o = t & 127;          // output index
        int quar = t >> 7;        // K quarter (0..3)
        int head = o >> 6, j = o & 63;
        const float* W3 = head ? aW3 : vW3;
        const float* hh = h2s + head * 256 + quar * 64;
        const float* wp = W3 + (quar * 64) * 64 + j;
        float s = 0.f;
#pragma unroll 8
        for (int kq = 0; kq < 64; kq++) s = fmaf(hh[kq], wp[kq * 64], s);
        part[o][quar] = s;
    }
    __syncthreads();
    if (t < 128) {
        int head = t >> 6, j = t & 63;
        float s = (part[t][0] + part[t][1]) + (part[t][2] + part[t][3])
                + (head ? ab3[j] : vb3[j]);
        h3s[t] = fmaxf(s, 0.f);
    }
    __syncthreads();

    // L4: 9 dots of length 64
    if (t < 9) {
        const float* hrow = &h3s[(t == 0) ? 0 : 64];
        float s = (t == 0) ? vb4[0] : ab4[t - 1];
        if (t == 0) {
#pragma unroll 8
            for (int c = 0; c < 64; c++) s = fmaf(hrow[c], vW4[c], s);
        } else {
#pragma unroll 8
            for (int c = 0; c < 64; c++) s = fmaf(hrow[c], aW4[c * A_DIM + (t - 1)], s);
        }
        res[t] = s;
    }
    __syncthreads();
    if (t < 8) {
        float m = 0.f;
#pragma unroll
        for (int q = 1; q < 9; q++) m += res[q];
        m *= 0.125f;
        out[b * A_DIM + t] = res[0] + res[1 + t] - m;
    }
}

// ---------------- launch ----------------
extern "C" void kernel_launch(void* const* d_in, const int* in_sizes, int n_in,
                              void* d_out, int out_size) {
    const float* x       = (const float*)d_in[0];
    const int*   ei      = (const int*)  d_in[1];
    const int*   tls     = (const int*)  d_in[2];
    const float* W       = (const float*)d_in[3];
    const float* att_src = (const float*)d_in[4];
    const float* att_dst = (const float*)d_in[5];
    const float* b_gat   = (const float*)d_in[6];
    const float* vW1 = (const float*)d_in[7];  const float* vb1 = (const float*)d_in[8];
    const float* vW2 = (const float*)d_in[9];  const float* vb2 = (const float*)d_in[10];
    const float* vW3 = (const float*)d_in[11]; const float* vb3 = (const float*)d_in[12];
    const float* vW4 = (const float*)d_in[13]; const float* vb4 = (const float*)d_in[14];
    const float* aW1 = (const float*)d_in[15]; const float* ab1 = (const float*)d_in[16];
    const float* aW2 = (const float*)d_in[17]; const float* ab2 = (const float*)d_in[18];
    const float* aW3 = (const float*)d_in[19]; const float* ab3 = (const float*)d_in[20];
    const float* aW4 = (const float*)d_in[21]; const float* ab4 = (const float*)d_in[22];

    float* h1 = nullptr; float* h2 = nullptr; float* ft = nullptr;
    cudaGetSymbolAddress((void**)&h1, g_h1);
    cudaGetSymbolAddress((void**)&h2, g_h2);
    cudaGetSymbolAddress((void**)&ft, g_feats);

    k_pre<<<2420, 256>>>(x, W, att_src, att_dst, ei, tls, vW1, aW1, vW2, aW2, vW3, aW3);
    k_agg<<<NSLOTS, 256>>>(x, W, tls, b_gat);

    // L1: feats[64,1024] @ {vW1,aW1}[1024,1024] -> RED h1 (raw). KC=16, 2048 blocks.
    k_gemm<16><<<dim3(16, 64, 2), 128>>>(ft, 0, 1024, 0, nullptr, nullptr, vW1, aW1, h1, 1024);
    // L2: relu(h1+b1)[64,1024/head] @ {vW2,aW2}[1024,256] -> RED h2. KC=16, 512 blocks.
    k_gemm<16><<<dim3(4, 64, 2), 128>>>(h1, 1, 2048, 1024, vb1, ab1, vW2, aW2, h2, 256);
    // L2-epilogue + L3 + L4 + combine, per graph
    k_tail<<<BGRAPH, 512>>>(vb2, ab2, vW3, vb3, aW3, ab3, vW4, vb4, aW4, ab4, (float*)d_out);
}